// round 6
// baseline (speedup 1.0000x reference)
#include <cuda_runtime.h>
#include <cstdint>
#include <cstddef>

// ---------------------------------------------------------------------------
// Fused concat-linear via int8 limb-decomposition on mma.sync.m16n8k32.s8.
//   x = a1/16 + a0/4096 ; W = b1/1024 + b0/262144  (int8 limbs)
//   y = S1/16384 + S2/4194304 + bias,  S1 = sum a1b1, S2 = sum (a1b0 + a0b1)
// Integer MMAs are exact; only quantization + dropped a0b0 term contribute
// error (~2.8e-4 rel, budget 1e-3).
// M=8192 N=12288 K=4096; out = 3 segments of H=4096 along o.
// ---------------------------------------------------------------------------

#define MDIM 8192
#define NDIM 12288
#define KDIM 4096
#define HDIM 4096

static constexpr int MT16 = MDIM / 16;     // 512
static constexpr int NT8  = NDIM / 8;      // 1536
static constexpr int KC32 = KDIM / 32;     // 128

// Packed limb scratch (fragment-ordered).
// A unit (kc32, mt16): 32 lanes x 4 words(16B).  word q, lane l:
//   q0: row mt*16+(l>>2),   k kc32*32+(l&3)*4 + 0..3
//   q1: row +8,  same k ;  q2: row, k+16 ;  q3: row+8, k+16
__device__ uint32_t g_A1[(size_t)KC32 * MT16 * 128];   // 33.5 MB
__device__ uint32_t g_A0[(size_t)KC32 * MT16 * 128];
// B unit (kc32, nt8): 32 lanes x 2 words(8B).  q0: n nt*8+(l>>2), k (l&3)*4+0..3 ; q1: k+16
__device__ uint32_t g_B1[(size_t)KC32 * NT8 * 64];     // 50 MB
__device__ uint32_t g_B0[(size_t)KC32 * NT8 * 64];

static constexpr int STAGES = 4;
static constexpr int THREADS = 256;
static constexpr int STAGE_BYTES = 32768;              // A 16KB + B 16KB
static constexpr int SMEM_BYTES = STAGES * STAGE_BYTES; // 131072

static constexpr int TILES_M = MDIM / 128;   // 64
static constexpr int TILES_N = NDIM / 128;   // 96
static constexpr int GROUP_M = 16;

__device__ __forceinline__ uint32_t smem_u32(const void* p) {
    return (uint32_t)__cvta_generic_to_shared(p);
}
__device__ __forceinline__ void cp16(uint32_t dst, const void* src) {
    asm volatile("cp.async.cg.shared.global [%0], [%1], 16;" :: "r"(dst), "l"(src));
}
__device__ __forceinline__ void mma_s8(int* c, const uint32_t* a, const uint32_t* b) {
    asm volatile(
        "mma.sync.aligned.m16n8k32.row.col.s32.s8.s8.s32 "
        "{%0,%1,%2,%3}, {%4,%5,%6,%7}, {%8,%9}, {%0,%1,%2,%3};"
        : "+r"(c[0]), "+r"(c[1]), "+r"(c[2]), "+r"(c[3])
        : "r"(a[0]), "r"(a[1]), "r"(a[2]), "r"(a[3]), "r"(b[0]), "r"(b[1]));
}

// quantize: s = x*scale; hi = rint(s) clamp +-127; lo = rint((s-hi)*256) clamp +-127
__device__ __forceinline__ void quant(float x, float scale, int& hi, int& lo) {
    float s = x * scale;
    float h = rintf(s);
    h = fminf(fmaxf(h, -127.f), 127.f);
    float l = rintf((s - h) * 256.f);
    l = fminf(fmaxf(l, -127.f), 127.f);
    hi = (int)h; lo = (int)l;
}
__device__ __forceinline__ uint32_t pack4(int b0, int b1, int b2, int b3) {
    return (uint32_t)(b0 & 255) | ((uint32_t)(b1 & 255) << 8) |
           ((uint32_t)(b2 & 255) << 16) | ((uint32_t)(b3 & 255) << 24);
}
__device__ __forceinline__ void quant_word(const float4 v, float scale,
                                           uint32_t& whi, uint32_t& wlo) {
    int h0, l0, h1, l1, h2, l2, h3, l3;
    quant(v.x, scale, h0, l0); quant(v.y, scale, h1, l1);
    quant(v.z, scale, h2, l2); quant(v.w, scale, h3, l3);
    whi = pack4(h0, h1, h2, h3);
    wlo = pack4(l0, l1, l2, l3);
}

// ---------------- pack kernels ----------------
// grid (64, 128): one thread per (kc32=by, mt, lane) A unit row.
__global__ __launch_bounds__(256)
void pack_a(const float* __restrict__ src, uint32_t* __restrict__ dA1,
            uint32_t* __restrict__ dA0) {
    const uint32_t inner = blockIdx.x * 256u + threadIdx.x;   // < 16384
    const int lane = inner & 31;
    const int mt   = inner >> 5;           // 0..511
    const int kc32 = blockIdx.y;           // 0..127
    const int r0 = mt * 16 + (lane >> 2);
    const int k0 = kc32 * 32 + (lane & 3) * 4;

    float4 v00 = *reinterpret_cast<const float4*>(src + (size_t)r0 * KDIM + k0);
    float4 v10 = *reinterpret_cast<const float4*>(src + (size_t)(r0 + 8) * KDIM + k0);
    float4 v01 = *reinterpret_cast<const float4*>(src + (size_t)r0 * KDIM + k0 + 16);
    float4 v11 = *reinterpret_cast<const float4*>(src + (size_t)(r0 + 8) * KDIM + k0 + 16);

    uint4 hi, lo;
    quant_word(v00, 16.f, hi.x, lo.x);
    quant_word(v10, 16.f, hi.y, lo.y);
    quant_word(v01, 16.f, hi.z, lo.z);
    quant_word(v11, 16.f, hi.w, lo.w);

    const size_t u = ((size_t)kc32 * MT16 + mt) * 32 + lane;
    reinterpret_cast<uint4*>(dA1)[u] = hi;
    reinterpret_cast<uint4*>(dA0)[u] = lo;
}
// grid (192, 128): one thread per (kc32=by, nt8, lane) B unit row.
__global__ __launch_bounds__(256)
void pack_b(const float* __restrict__ src, uint32_t* __restrict__ dB1,
            uint32_t* __restrict__ dB0) {
    const uint32_t inner = blockIdx.x * 256u + threadIdx.x;   // < 49152
    const int lane = inner & 31;
    const int nt   = inner >> 5;           // 0..1535
    const int kc32 = blockIdx.y;
    const int n = nt * 8 + (lane >> 2);
    const int k0 = kc32 * 32 + (lane & 3) * 4;

    float4 v0 = *reinterpret_cast<const float4*>(src + (size_t)n * KDIM + k0);
    float4 v1 = *reinterpret_cast<const float4*>(src + (size_t)n * KDIM + k0 + 16);

    uint2 hi, lo;
    quant_word(v0, 1024.f, hi.x, lo.x);
    quant_word(v1, 1024.f, hi.y, lo.y);

    const size_t u = ((size_t)kc32 * NT8 + nt) * 32 + lane;
    reinterpret_cast<uint2*>(dB1)[u] = hi;
    reinterpret_cast<uint2*>(dB0)[u] = lo;
}

// ---------------- GEMM: CTA 128x128, BK=64, warps 2x4 of 64x32 ----------------
// stage layout (bytes): A [ks2][limb2][mt8][lane*16] = 16KB ; B [ks2][limb2][nt16][lane*8] = 16KB
__global__ __launch_bounds__(THREADS, 1)
void gemm_s8(const uint32_t* __restrict__ A1, const uint32_t* __restrict__ A0,
             const uint32_t* __restrict__ B1, const uint32_t* __restrict__ B0,
             const float* __restrict__ bias, float* __restrict__ out)
{
    extern __shared__ uint32_t smemu[];
    const uint32_t sbase = smem_u32(smemu);

    const int tid  = threadIdx.x;
    const int wid  = tid >> 5;
    const int lane = tid & 31;
    const int gid  = lane >> 2;
    const int tig  = lane & 3;
    const int warp_m = wid & 1;      // 64 rows
    const int warp_n = wid >> 1;     // 32 cols

    const int bid  = blockIdx.x;
    const int band = bid / (GROUP_M * TILES_N);
    const int rem  = bid % (GROUP_M * TILES_N);
    const int mt   = band * GROUP_M + (rem % GROUP_M);
    const int nt   = rem / GROUP_M;
    const int m0 = mt * 128;
    const int n0 = nt * 128;

    const int mtBase = m0 >> 4;      // 8 consecutive mt16 units
    const int ntBase = n0 >> 3;      // 16 consecutive nt8 units

    int acc1[4][4][4], acc2[4][4][4];
#pragma unroll
    for (int mi = 0; mi < 4; mi++)
#pragma unroll
        for (int ni = 0; ni < 4; ni++)
#pragma unroll
            for (int q = 0; q < 4; q++) { acc1[mi][ni][q] = 0; acc2[mi][ni][q] = 0; }

    const int KT = KDIM / 64;        // 64

    // stage loader: 4KB chunks, 256 threads x 16B each
    auto load_stage = [&](int slot, int kt) {
        const uint32_t sA = sbase + slot * STAGE_BYTES;
        const uint32_t sB = sA + 16384;
#pragma unroll
        for (int ks = 0; ks < 2; ks++) {
            const size_t kc = (size_t)(2 * kt + ks);
            const uint32_t* aH = A1 + (kc * MT16 + mtBase) * 128 + tid * 4;
            const uint32_t* aL = A0 + (kc * MT16 + mtBase) * 128 + tid * 4;
            const uint32_t* bH = B1 + (kc * NT8 + ntBase) * 64 + tid * 4;
            const uint32_t* bL = B0 + (kc * NT8 + ntBase) * 64 + tid * 4;
            cp16(sA + (ks * 2 + 0) * 4096 + tid * 16, aH);
            cp16(sA + (ks * 2 + 1) * 4096 + tid * 16, aL);
            cp16(sB + (ks * 2 + 0) * 4096 + tid * 16, bH);
            cp16(sB + (ks * 2 + 1) * 4096 + tid * 16, bL);
        }
        asm volatile("cp.async.commit_group;" ::: "memory");
    };

#pragma unroll
    for (int s = 0; s < STAGES - 1; s++) load_stage(s, s);

    for (int kt = 0; kt < KT; kt++) {
        asm volatile("cp.async.wait_group %0;" :: "n"(STAGES - 2) : "memory");
        __syncthreads();

        const int kin = kt + STAGES - 1;
        if (kin < KT) load_stage(kin % STAGES, kin);
        else asm volatile("cp.async.commit_group;" ::: "memory");

        const uint32_t* st = smemu + (kt % STAGES) * (STAGE_BYTES / 4);
        const uint32_t* stB = st + 4096;
#pragma unroll
        for (int ks = 0; ks < 2; ks++) {
            uint4 a1f[4], a0f[4];
            uint2 b1f[4], b0f[4];
#pragma unroll
            for (int mi = 0; mi < 4; mi++) {
                const int u = (warp_m * 4 + mi) * 128 + lane * 4;
                a1f[mi] = *reinterpret_cast<const uint4*>(st + (ks * 2 + 0) * 1024 + u);
                a0f[mi] = *reinterpret_cast<const uint4*>(st + (ks * 2 + 1) * 1024 + u);
            }
#pragma unroll
            for (int ni = 0; ni < 4; ni++) {
                const int u = (warp_n * 4 + ni) * 64 + lane * 2;
                b1f[ni] = *reinterpret_cast<const uint2*>(stB + (ks * 2 + 0) * 1024 + u);
                b0f[ni] = *reinterpret_cast<const uint2*>(stB + (ks * 2 + 1) * 1024 + u);
            }
#pragma unroll
            for (int mi = 0; mi < 4; mi++) {
                const uint32_t aH[4] = {a1f[mi].x, a1f[mi].y, a1f[mi].z, a1f[mi].w};
                const uint32_t aL[4] = {a0f[mi].x, a0f[mi].y, a0f[mi].z, a0f[mi].w};
#pragma unroll
                for (int ni = 0; ni < 4; ni++) {
                    const uint32_t bH[2] = {b1f[ni].x, b1f[ni].y};
                    const uint32_t bL[2] = {b0f[ni].x, b0f[ni].y};
                    mma_s8(acc1[mi][ni], aH, bH);
                    mma_s8(acc2[mi][ni], aH, bL);
                    mma_s8(acc2[mi][ni], aL, bH);
                }
            }
        }
    }

    // ---- epilogue: scale-combine + bias + segmented store ----
    const float C1 = 1.f / 16384.f;
    const float C2 = 1.f / 4194304.f;
    const int seg  = n0 / HDIM;
    const int nloc = n0 % HDIM;
    float* outseg = out + (size_t)seg * MDIM * HDIM;

#pragma unroll
    for (int ni = 0; ni < 4; ni++) {
        const int gn = n0 + warp_n * 32 + ni * 8 + 2 * tig;
        const float bb0 = __ldg(bias + gn);
        const float bb1 = __ldg(bias + gn + 1);
        const int cn = nloc + warp_n * 32 + ni * 8 + 2 * tig;
#pragma unroll
        for (int mi = 0; mi < 4; mi++) {
            const int gm = m0 + warp_m * 64 + mi * 16 + gid;
            float2 v0, v1;
            v0.x = (float)acc1[mi][ni][0] * C1 + (float)acc2[mi][ni][0] * C2 + bb0;
            v0.y = (float)acc1[mi][ni][1] * C1 + (float)acc2[mi][ni][1] * C2 + bb1;
            v1.x = (float)acc1[mi][ni][2] * C1 + (float)acc2[mi][ni][2] * C2 + bb0;
            v1.y = (float)acc1[mi][ni][3] * C1 + (float)acc2[mi][ni][3] * C2 + bb1;
            *reinterpret_cast<float2*>(outseg + (size_t)gm * HDIM + cn)       = v0;
            *reinterpret_cast<float2*>(outseg + (size_t)(gm + 8) * HDIM + cn) = v1;
        }
    }
}

extern "C" void kernel_launch(void* const* d_in, const int* in_sizes, int n_in,
                              void* d_out, int out_size)
{
    const float* x = (const float*)d_in[0];
    const float* W = (const float*)d_in[1];
    const float* b = (const float*)d_in[2];
    float* out = (float*)d_out;

    void *a1, *a0, *b1, *b0;
    cudaGetSymbolAddress(&a1, g_A1);
    cudaGetSymbolAddress(&a0, g_A0);
    cudaGetSymbolAddress(&b1, g_B1);
    cudaGetSymbolAddress(&b0, g_B0);

    pack_a<<<dim3(64, 128), 256>>>(x, (uint32_t*)a1, (uint32_t*)a0);
    pack_b<<<dim3(192, 128), 256>>>(W, (uint32_t*)b1, (uint32_t*)b0);

    cudaFuncSetAttribute(gemm_s8, cudaFuncAttributeMaxDynamicSharedMemorySize, SMEM_BYTES);
    gemm_s8<<<TILES_M * TILES_N, THREADS, SMEM_BYTES>>>(
        (const uint32_t*)a1, (const uint32_t*)a0,
        (const uint32_t*)b1, (const uint32_t*)b0, b, out);
}

// round 7
// speedup vs baseline: 3.6754x; 3.6754x over previous
#include <cuda_runtime.h>
#include <cstdint>
#include <cstddef>

// ---------------------------------------------------------------------------
// Fused concat-linear, single-pass TF32 mma.sync, fragment-packed operands.
// Round 7: 256x128 CTA tile (256 threads, 4x2 warps of 64x64), 4-stage
// cp.async. Arithmetic intensity up 2.7x -> L2 streaming no longer co-binds.
// (Round 6 int8-limb experiment: s8 mma.sync is ~0.5x tf32 rate here; reverted.)
// ---------------------------------------------------------------------------

#define MDIM 8192
#define NDIM 12288
#define KDIM 4096
#define HDIM 4096

static constexpr int STAGES = 4;
static constexpr int THREADS = 256;

static constexpr int MT16 = MDIM / 16;        // 512
static constexpr int NT16 = NDIM / 16;        // 768

// packed scratch: [kc32][t16][kc8(4)][lane(32)][q(4)] words (validated R4/R5)
__device__ uint32_t g_Apack[(size_t)(KDIM / 32) * MT16 * 512];
__device__ uint32_t g_Bpack[(size_t)(KDIM / 32) * NT16 * 512];

static constexpr int STAGE_WORDS = 12288;                      // A 32KB + B 16KB
static constexpr int STAGE_BYTES = STAGE_WORDS * 4;            // 49152
static constexpr int SMEM_BYTES  = STAGES * STAGE_BYTES;       // 196608

static constexpr int TILES_M = MDIM / 256;    // 32
static constexpr int TILES_N = NDIM / 128;    // 96
static constexpr int GROUP_M = 8;

__device__ __forceinline__ uint32_t smem_u32(const void* p) {
    return (uint32_t)__cvta_generic_to_shared(p);
}
__device__ __forceinline__ void cp16(uint32_t dst, const void* src) {
    asm volatile("cp.async.cg.shared.global [%0], [%1], 16;" :: "r"(dst), "l"(src));
}
__device__ __forceinline__ uint32_t f2tf32(float x) {
    uint32_t r;
    asm("cvt.rna.tf32.f32 %0, %1;" : "=r"(r) : "f"(x));
    return r;
}
__device__ __forceinline__ void mma_tf32(float* c, const uint32_t* a, const uint32_t* b) {
    asm volatile(
        "mma.sync.aligned.m16n8k8.row.col.f32.tf32.tf32.f32 "
        "{%0,%1,%2,%3}, {%4,%5,%6,%7}, {%8,%9}, {%0,%1,%2,%3};"
        : "+f"(c[0]), "+f"(c[1]), "+f"(c[2]), "+f"(c[3])
        : "r"(a[0]), "r"(a[1]), "r"(a[2]), "r"(a[3]), "r"(b[0]), "r"(b[1]));
}

// ---------------- pack kernels (unchanged; validated R4/R5) ----------------
__global__ __launch_bounds__(256)
void pack_a(const float* __restrict__ src, uint32_t* __restrict__ dst) {
    const uint32_t idx = blockIdx.x * 256u + threadIdx.x;
    const int lane = idx & 31, kc8 = (idx >> 5) & 3;
    const int t16 = (idx >> 7) & 511, kc32 = idx >> 16;
    const int gid = lane >> 2, tig = lane & 3;
    const size_t rbase = (size_t)(t16 * 16 + gid) * KDIM + kc32 * 32 + kc8 * 8 + tig;
    uint4 w;
    w.x = f2tf32(src[rbase]);
    w.y = f2tf32(src[rbase + 8 * (size_t)KDIM]);
    w.z = f2tf32(src[rbase + 4]);
    w.w = f2tf32(src[rbase + 8 * (size_t)KDIM + 4]);
    reinterpret_cast<uint4*>(dst)[idx] = w;
}
__global__ __launch_bounds__(256)
void pack_b(const float* __restrict__ src, uint32_t* __restrict__ dst) {
    const uint32_t idx = blockIdx.x * 256u + threadIdx.x;
    const int lane = idx & 31, kc8 = (idx >> 5) & 3;
    const int kc32 = idx / 98304;
    const int t16  = (idx % 98304) >> 7;
    const int gid = lane >> 2, tig = lane & 3;
    const size_t rbase = (size_t)(t16 * 16 + gid) * KDIM + kc32 * 32 + kc8 * 8 + tig;
    uint4 w;
    w.x = f2tf32(src[rbase]);
    w.y = f2tf32(src[rbase + 8 * (size_t)KDIM]);
    w.z = f2tf32(src[rbase + 4]);
    w.w = f2tf32(src[rbase + 8 * (size_t)KDIM + 4]);
    reinterpret_cast<uint4*>(dst)[idx] = w;
}

// ---------------- GEMM: 256x128 tile, 8 warps of 64x64 ----------------
__global__ __launch_bounds__(THREADS, 1)
void gemm_tf32(const uint32_t* __restrict__ Apack,
               const uint32_t* __restrict__ Bpack,
               const float* __restrict__ bias,
               float* __restrict__ out)
{
    extern __shared__ uint32_t smemu[];
    const uint32_t sbase = smem_u32(smemu);

    const int tid  = threadIdx.x;
    const int wid  = tid >> 5;
    const int lane = tid & 31;
    const int gid  = lane >> 2;
    const int tig  = lane & 3;
    const int warp_m = wid & 3;     // 4 warps along M: 64 rows each (256 total)
    const int warp_n = wid >> 2;    // 2 warps along N: 64 cols each (128 total)

    const int bid  = blockIdx.x;
    const int band = bid / (GROUP_M * TILES_N);
    const int rem  = bid % (GROUP_M * TILES_N);
    const int mt   = band * GROUP_M + (rem % GROUP_M);
    const int nt   = rem / GROUP_M;
    const int m0 = mt * 256;
    const int n0 = nt * 128;

    // packed gmem stage sources (contiguous per kc32)
    const uint32_t* Asrc = Apack + (size_t)(m0 >> 4) * 512 + tid * 4;   // 16 units
    const uint32_t* Bsrc = Bpack + (size_t)(n0 >> 4) * 512 + tid * 4;   // 8 units
    const size_t AstageStep = (size_t)MT16 * 512;
    const size_t BstageStep = (size_t)NT16 * 512;

    float acc[4][8][4];
#pragma unroll
    for (int mi = 0; mi < 4; mi++)
#pragma unroll
        for (int ni = 0; ni < 8; ni++)
#pragma unroll
            for (int q = 0; q < 4; q++) acc[mi][ni][q] = 0.0f;

    const int KT = KDIM / 32;       // 128

    auto load_stage = [&](int slot, int kt) {
        const uint32_t sA = sbase + (uint32_t)slot * STAGE_BYTES;
        const uint32_t sB = sA + 32768;
#pragma unroll
        for (int i = 0; i < 8; i++)
            cp16(sA + i * 4096 + tid * 16, Asrc + (size_t)kt * AstageStep + i * 1024);
#pragma unroll
        for (int i = 0; i < 4; i++)
            cp16(sB + i * 4096 + tid * 16, Bsrc + (size_t)kt * BstageStep + i * 1024);
        asm volatile("cp.async.commit_group;" ::: "memory");
    };

#pragma unroll
    for (int s = 0; s < STAGES - 1; s++) load_stage(s, s);

    for (int kt = 0; kt < KT; kt++) {
        asm volatile("cp.async.wait_group %0;" :: "n"(STAGES - 2) : "memory");
        __syncthreads();

        const int kin = kt + STAGES - 1;
        if (kin < KT) load_stage(kin % STAGES, kin);
        else asm volatile("cp.async.commit_group;" ::: "memory");

        // stage layout: A = [mtile(16)][ks(4)][lane(32)][q(4)], B = [ntile(8)][ks(4)][lane][q]
        const uint32_t* as = smemu + (kt % STAGES) * STAGE_WORDS;
        const uint32_t* bs = as + 8192;
#pragma unroll
        for (int ks = 0; ks < 4; ks++) {
            uint4 af[4], bf[4];
#pragma unroll
            for (int mi = 0; mi < 4; mi++)
                af[mi] = *reinterpret_cast<const uint4*>(
                    as + (((warp_m * 4 + mi) * 4 + ks) << 7) + lane * 4);
#pragma unroll
            for (int nj = 0; nj < 4; nj++)
                bf[nj] = *reinterpret_cast<const uint4*>(
                    bs + (((warp_n * 4 + nj) * 4 + ks) << 7) + lane * 4);

#pragma unroll
            for (int mi = 0; mi < 4; mi++) {
                const uint32_t afr[4] = {af[mi].x, af[mi].y, af[mi].z, af[mi].w};
#pragma unroll
                for (int nj = 0; nj < 4; nj++) {
                    const uint32_t b0[2] = {bf[nj].x, bf[nj].z};
                    const uint32_t b1[2] = {bf[nj].y, bf[nj].w};
                    mma_tf32(acc[mi][nj * 2 + 0], afr, b0);
                    mma_tf32(acc[mi][nj * 2 + 1], afr, b1);
                }
            }
        }
    }

    // ---- epilogue: bias + segmented store ----
    const int seg  = n0 / HDIM;     // 128-wide N tile never straddles a segment
    const int nloc = n0 % HDIM;
    float* outseg = out + (size_t)seg * MDIM * HDIM;

#pragma unroll
    for (int ni = 0; ni < 8; ni++) {
        const int gn = n0 + warp_n * 64 + ni * 8 + 2 * tig;
        const float b0 = __ldg(bias + gn);
        const float b1 = __ldg(bias + gn + 1);
        const int cn = nloc + warp_n * 64 + ni * 8 + 2 * tig;
#pragma unroll
        for (int mi = 0; mi < 4; mi++) {
            const int gm = m0 + warp_m * 64 + mi * 16 + gid;
            float2 v0, v1;
            v0.x = acc[mi][ni][0] + b0;  v0.y = acc[mi][ni][1] + b1;
            v1.x = acc[mi][ni][2] + b0;  v1.y = acc[mi][ni][3] + b1;
            *reinterpret_cast<float2*>(outseg + (size_t)gm * HDIM + cn)       = v0;
            *reinterpret_cast<float2*>(outseg + (size_t)(gm + 8) * HDIM + cn) = v1;
        }
    }
}

extern "C" void kernel_launch(void* const* d_in, const int* in_sizes, int n_in,
                              void* d_out, int out_size)
{
    const float* x = (const float*)d_in[0];
    const float* W = (const float*)d_in[1];
    const float* b = (const float*)d_in[2];
    float* out = (float*)d_out;

    void *ap, *bp;
    cudaGetSymbolAddress(&ap, g_Apack);
    cudaGetSymbolAddress(&bp, g_Bpack);

    pack_a<<<32768, 256>>>(x, (uint32_t*)ap);
    pack_b<<<49152, 256>>>(W, (uint32_t*)bp);

    cudaFuncSetAttribute(gemm_tf32, cudaFuncAttributeMaxDynamicSharedMemorySize, SMEM_BYTES);
    gemm_tf32<<<TILES_M * TILES_N, THREADS, SMEM_BYTES>>>(
        (const uint32_t*)ap, (const uint32_t*)bp, b, out);
}

// round 8
// speedup vs baseline: 4.0275x; 1.0958x over previous
#include <cuda_runtime.h>
#include <cstdint>
#include <cstddef>

// ---------------------------------------------------------------------------
// Fused concat-linear, single-pass TF32 mma.sync, fragment-packed operands.
// Round 8: R5 config (128x128 tile, 128 thr, 2 CTA/SM, 64x64 warp tiles)
// + double-buffered fragment registers across ks (hides LDS->MMA latency)
// + cp.async issued after first fragment loads (critical path first).
// ---------------------------------------------------------------------------

#define MDIM 8192
#define NDIM 12288
#define KDIM 4096
#define HDIM 4096

static constexpr int STAGES = 3;
static constexpr int THREADS = 128;

static constexpr int MT16 = MDIM / 16;        // 512
static constexpr int NT16 = NDIM / 16;        // 768

// packed scratch: [kc32][t16][kc8(4)][lane(32)][q(4)] words (validated R4+)
__device__ uint32_t g_Apack[(size_t)(KDIM / 32) * MT16 * 512];
__device__ uint32_t g_Bpack[(size_t)(KDIM / 32) * NT16 * 512];

static constexpr int STAGE_WORDS = 8192;                       // A 16KB + B 16KB
static constexpr int SMEM_BYTES  = STAGES * STAGE_WORDS * 4;   // 98304

static constexpr int TILES_M = MDIM / 128;    // 64
static constexpr int TILES_N = NDIM / 128;    // 96
static constexpr int GROUP_M = 16;

__device__ __forceinline__ uint32_t smem_u32(const void* p) {
    return (uint32_t)__cvta_generic_to_shared(p);
}
__device__ __forceinline__ void cp16(uint32_t dst, const void* src) {
    asm volatile("cp.async.cg.shared.global [%0], [%1], 16;" :: "r"(dst), "l"(src));
}
__device__ __forceinline__ uint32_t f2tf32(float x) {
    uint32_t r;
    asm("cvt.rna.tf32.f32 %0, %1;" : "=r"(r) : "f"(x));
    return r;
}
__device__ __forceinline__ void mma_tf32(float* c, const uint32_t* a, const uint32_t* b) {
    asm volatile(
        "mma.sync.aligned.m16n8k8.row.col.f32.tf32.tf32.f32 "
        "{%0,%1,%2,%3}, {%4,%5,%6,%7}, {%8,%9}, {%0,%1,%2,%3};"
        : "+f"(c[0]), "+f"(c[1]), "+f"(c[2]), "+f"(c[3])
        : "r"(a[0]), "r"(a[1]), "r"(a[2]), "r"(a[3]), "r"(b[0]), "r"(b[1]));
}

// ---------------- pack kernels (unchanged; validated R4/R5) ----------------
__global__ __launch_bounds__(256)
void pack_a(const float* __restrict__ src, uint32_t* __restrict__ dst) {
    const uint32_t idx = blockIdx.x * 256u + threadIdx.x;
    const int lane = idx & 31, kc8 = (idx >> 5) & 3;
    const int t16 = (idx >> 7) & 511, kc32 = idx >> 16;
    const int gid = lane >> 2, tig = lane & 3;
    const size_t rbase = (size_t)(t16 * 16 + gid) * KDIM + kc32 * 32 + kc8 * 8 + tig;
    uint4 w;
    w.x = f2tf32(src[rbase]);
    w.y = f2tf32(src[rbase + 8 * (size_t)KDIM]);
    w.z = f2tf32(src[rbase + 4]);
    w.w = f2tf32(src[rbase + 8 * (size_t)KDIM + 4]);
    reinterpret_cast<uint4*>(dst)[idx] = w;
}
__global__ __launch_bounds__(256)
void pack_b(const float* __restrict__ src, uint32_t* __restrict__ dst) {
    const uint32_t idx = blockIdx.x * 256u + threadIdx.x;
    const int lane = idx & 31, kc8 = (idx >> 5) & 3;
    const int kc32 = idx / 98304;
    const int t16  = (idx % 98304) >> 7;
    const int gid = lane >> 2, tig = lane & 3;
    const size_t rbase = (size_t)(t16 * 16 + gid) * KDIM + kc32 * 32 + kc8 * 8 + tig;
    uint4 w;
    w.x = f2tf32(src[rbase]);
    w.y = f2tf32(src[rbase + 8 * (size_t)KDIM]);
    w.z = f2tf32(src[rbase + 4]);
    w.w = f2tf32(src[rbase + 8 * (size_t)KDIM + 4]);
    reinterpret_cast<uint4*>(dst)[idx] = w;
}

// ---------------- GEMM: 128x128 tile, 4 warps of 64x64, ks-pipelined ----------------
__global__ __launch_bounds__(THREADS, 2)
void gemm_tf32(const uint32_t* __restrict__ Apack,
               const uint32_t* __restrict__ Bpack,
               const float* __restrict__ bias,
               float* __restrict__ out)
{
    extern __shared__ uint32_t smemu[];
    const uint32_t sbase = smem_u32(smemu);

    const int tid  = threadIdx.x;
    const int wid  = tid >> 5;
    const int lane = tid & 31;
    const int gid  = lane >> 2;
    const int tig  = lane & 3;
    const int warp_m = wid & 1;     // 64 rows
    const int warp_n = wid >> 1;    // 64 cols

    const int bid  = blockIdx.x;
    const int band = bid / (GROUP_M * TILES_N);
    const int rem  = bid % (GROUP_M * TILES_N);
    const int mt   = band * GROUP_M + (rem % GROUP_M);
    const int nt   = rem / GROUP_M;
    const int m0 = mt * 128;
    const int n0 = nt * 128;

    const uint32_t* Asrc = Apack + (size_t)(m0 >> 4) * 512 + tid * 4;
    const uint32_t* Bsrc = Bpack + (size_t)(n0 >> 4) * 512 + tid * 4;
    const size_t AstageStep = (size_t)MT16 * 512;
    const size_t BstageStep = (size_t)NT16 * 512;

    float acc[4][8][4];
#pragma unroll
    for (int mi = 0; mi < 4; mi++)
#pragma unroll
        for (int ni = 0; ni < 8; ni++)
#pragma unroll
            for (int q = 0; q < 4; q++) acc[mi][ni][q] = 0.0f;

    const int KT = KDIM / 32;    // 128

#pragma unroll
    for (int s = 0; s < STAGES - 1; s++) {
        const uint32_t a_s = sbase + (uint32_t)(s * STAGE_WORDS) * 4;
        const uint32_t b_s = a_s + 4096 * 4;
#pragma unroll
        for (int i = 0; i < 8; i++) {
            cp16(a_s + tid * 16 + i * 2048, Asrc + (size_t)s * AstageStep + i * 512);
            cp16(b_s + tid * 16 + i * 2048, Bsrc + (size_t)s * BstageStep + i * 512);
        }
        asm volatile("cp.async.commit_group;" ::: "memory");
    }

    const int aBase = warp_m * 4;   // mtile index base
    const int bBase = warp_n * 4;   // ntile index base

    for (int kt = 0; kt < KT; kt++) {
        asm volatile("cp.async.wait_group %0;" :: "n"(STAGES - 2) : "memory");
        __syncthreads();

        // stage layout: A = [mtile(8)][ks(4)][lane(32)][q(4)], B likewise
        const uint32_t* as = smemu + (kt % STAGES) * STAGE_WORDS;
        const uint32_t* bs = as + 4096;

        // ---- critical path first: fragments for ks=0 ----
        uint4 af[2][4], bf[2][4];
#pragma unroll
        for (int mi = 0; mi < 4; mi++)
            af[0][mi] = *reinterpret_cast<const uint4*>(
                as + (((aBase + mi) * 4 + 0) << 7) + lane * 4);
#pragma unroll
        for (int nj = 0; nj < 4; nj++)
            bf[0][nj] = *reinterpret_cast<const uint4*>(
                bs + (((bBase + nj) * 4 + 0) << 7) + lane * 4);

        // ---- then issue next-stage loads ----
        const int kin = kt + STAGES - 1;
        if (kin < KT) {
            const int s = kin % STAGES;
            const uint32_t a_s = sbase + (uint32_t)(s * STAGE_WORDS) * 4;
            const uint32_t b_s = a_s + 4096 * 4;
#pragma unroll
            for (int i = 0; i < 8; i++) {
                cp16(a_s + tid * 16 + i * 2048, Asrc + (size_t)kin * AstageStep + i * 512);
                cp16(b_s + tid * 16 + i * 2048, Bsrc + (size_t)kin * BstageStep + i * 512);
            }
        }
        asm volatile("cp.async.commit_group;" ::: "memory");

        // ---- ks loop, fragments double-buffered ----
#pragma unroll
        for (int ks = 0; ks < 4; ks++) {
            const int cur = ks & 1;
            const int nxt = cur ^ 1;
            if (ks < 3) {
#pragma unroll
                for (int mi = 0; mi < 4; mi++)
                    af[nxt][mi] = *reinterpret_cast<const uint4*>(
                        as + (((aBase + mi) * 4 + ks + 1) << 7) + lane * 4);
#pragma unroll
                for (int nj = 0; nj < 4; nj++)
                    bf[nxt][nj] = *reinterpret_cast<const uint4*>(
                        bs + (((bBase + nj) * 4 + ks + 1) << 7) + lane * 4);
            }
#pragma unroll
            for (int mi = 0; mi < 4; mi++) {
                const uint32_t afr[4] = {af[cur][mi].x, af[cur][mi].y,
                                         af[cur][mi].z, af[cur][mi].w};
#pragma unroll
                for (int nj = 0; nj < 4; nj++) {
                    const uint32_t b0[2] = {bf[cur][nj].x, bf[cur][nj].z};
                    const uint32_t b1[2] = {bf[cur][nj].y, bf[cur][nj].w};
                    mma_tf32(acc[mi][nj * 2 + 0], afr, b0);
                    mma_tf32(acc[mi][nj * 2 + 1], afr, b1);
                }
            }
        }
    }

    // ---- epilogue: bias + segmented store ----
    const int seg  = n0 / HDIM;
    const int nloc = n0 % HDIM;
    float* outseg = out + (size_t)seg * MDIM * HDIM;

#pragma unroll
    for (int ni = 0; ni < 8; ni++) {
        const int gn = n0 + warp_n * 64 + ni * 8 + 2 * tig;
        const float b0 = __ldg(bias + gn);
        const float b1 = __ldg(bias + gn + 1);
        const int cn = nloc + warp_n * 64 + ni * 8 + 2 * tig;
#pragma unroll
        for (int mi = 0; mi < 4; mi++) {
            const int gm = m0 + warp_m * 64 + mi * 16 + gid;
            float2 v0, v1;
            v0.x = acc[mi][ni][0] + b0;  v0.y = acc[mi][ni][1] + b1;
            v1.x = acc[mi][ni][2] + b0;  v1.y = acc[mi][ni][3] + b1;
            *reinterpret_cast<float2*>(outseg + (size_t)gm * HDIM + cn)       = v0;
            *reinterpret_cast<float2*>(outseg + (size_t)(gm + 8) * HDIM + cn) = v1;
        }
    }
}

extern "C" void kernel_launch(void* const* d_in, const int* in_sizes, int n_in,
                              void* d_out, int out_size)
{
    const float* x = (const float*)d_in[0];
    const float* W = (const float*)d_in[1];
    const float* b = (const float*)d_in[2];
    float* out = (float*)d_out;

    void *ap, *bp;
    cudaGetSymbolAddress(&ap, g_Apack);
    cudaGetSymbolAddress(&bp, g_Bpack);

    pack_a<<<32768, 256>>>(x, (uint32_t*)ap);
    pack_b<<<49152, 256>>>(W, (uint32_t*)bp);

    cudaFuncSetAttribute(gemm_tf32, cudaFuncAttributeMaxDynamicSharedMemorySize, SMEM_BYTES);
    gemm_tf32<<<TILES_M * TILES_N, THREADS, SMEM_BYTES>>>(
        (const uint32_t*)ap, (const uint32_t*)bp, b, out);
}

// round 9
// speedup vs baseline: 4.8605x; 1.2068x over previous
#include <cuda_runtime.h>
#include <cstdint>
#include <cstddef>

// ---------------------------------------------------------------------------
// Fused concat-linear, single-pass TF32 mma.sync, fragment-packed operands.
// Round 9: barrier moved off the critical path. Per kt: ks0-ks2 compute with
// fragment prefetch, then wait+syncthreads (stage-kt reads already done),
// then prefetch next-kt ks0 fragments (stage kt+1 now published), then ks3
// MMAs cover the LDS latency. Warps resume MMAs immediately after barriers.
// ---------------------------------------------------------------------------

#define MDIM 8192
#define NDIM 12288
#define KDIM 4096
#define HDIM 4096

static constexpr int STAGES = 3;
static constexpr int THREADS = 128;

static constexpr int MT16 = MDIM / 16;        // 512
static constexpr int NT16 = NDIM / 16;        // 768

// packed scratch: [kc32][t16][kc8(4)][lane(32)][q(4)] words (validated R4+)
__device__ uint32_t g_Apack[(size_t)(KDIM / 32) * MT16 * 512];
__device__ uint32_t g_Bpack[(size_t)(KDIM / 32) * NT16 * 512];

static constexpr int STAGE_WORDS = 8192;                       // A 16KB + B 16KB
static constexpr int SMEM_BYTES  = STAGES * STAGE_WORDS * 4;   // 98304

static constexpr int TILES_M = MDIM / 128;    // 64
static constexpr int TILES_N = NDIM / 128;    // 96
static constexpr int GROUP_M = 16;

__device__ __forceinline__ uint32_t smem_u32(const void* p) {
    return (uint32_t)__cvta_generic_to_shared(p);
}
__device__ __forceinline__ void cp16(uint32_t dst, const void* src) {
    asm volatile("cp.async.cg.shared.global [%0], [%1], 16;" :: "r"(dst), "l"(src));
}
__device__ __forceinline__ uint32_t f2tf32(float x) {
    uint32_t r;
    asm("cvt.rna.tf32.f32 %0, %1;" : "=r"(r) : "f"(x));
    return r;
}
__device__ __forceinline__ void mma_tf32(float* c, const uint32_t* a, const uint32_t* b) {
    asm volatile(
        "mma.sync.aligned.m16n8k8.row.col.f32.tf32.tf32.f32 "
        "{%0,%1,%2,%3}, {%4,%5,%6,%7}, {%8,%9}, {%0,%1,%2,%3};"
        : "+f"(c[0]), "+f"(c[1]), "+f"(c[2]), "+f"(c[3])
        : "r"(a[0]), "r"(a[1]), "r"(a[2]), "r"(a[3]), "r"(b[0]), "r"(b[1]));
}

// ---------------- pack kernels (unchanged; validated R4/R5) ----------------
__global__ __launch_bounds__(256)
void pack_a(const float* __restrict__ src, uint32_t* __restrict__ dst) {
    const uint32_t idx = blockIdx.x * 256u + threadIdx.x;
    const int lane = idx & 31, kc8 = (idx >> 5) & 3;
    const int t16 = (idx >> 7) & 511, kc32 = idx >> 16;
    const int gid = lane >> 2, tig = lane & 3;
    const size_t rbase = (size_t)(t16 * 16 + gid) * KDIM + kc32 * 32 + kc8 * 8 + tig;
    uint4 w;
    w.x = f2tf32(src[rbase]);
    w.y = f2tf32(src[rbase + 8 * (size_t)KDIM]);
    w.z = f2tf32(src[rbase + 4]);
    w.w = f2tf32(src[rbase + 8 * (size_t)KDIM + 4]);
    reinterpret_cast<uint4*>(dst)[idx] = w;
}
__global__ __launch_bounds__(256)
void pack_b(const float* __restrict__ src, uint32_t* __restrict__ dst) {
    const uint32_t idx = blockIdx.x * 256u + threadIdx.x;
    const int lane = idx & 31, kc8 = (idx >> 5) & 3;
    const int kc32 = idx / 98304;
    const int t16  = (idx % 98304) >> 7;
    const int gid = lane >> 2, tig = lane & 3;
    const size_t rbase = (size_t)(t16 * 16 + gid) * KDIM + kc32 * 32 + kc8 * 8 + tig;
    uint4 w;
    w.x = f2tf32(src[rbase]);
    w.y = f2tf32(src[rbase + 8 * (size_t)KDIM]);
    w.z = f2tf32(src[rbase + 4]);
    w.w = f2tf32(src[rbase + 8 * (size_t)KDIM + 4]);
    reinterpret_cast<uint4*>(dst)[idx] = w;
}

// ---------------- GEMM: 128x128 tile, 4 warps of 64x64 ----------------
__global__ __launch_bounds__(THREADS, 2)
void gemm_tf32(const uint32_t* __restrict__ Apack,
               const uint32_t* __restrict__ Bpack,
               const float* __restrict__ bias,
               float* __restrict__ out)
{
    extern __shared__ uint32_t smemu[];
    const uint32_t sbase = smem_u32(smemu);

    const int tid  = threadIdx.x;
    const int wid  = tid >> 5;
    const int lane = tid & 31;
    const int gid  = lane >> 2;
    const int tig  = lane & 3;
    const int warp_m = wid & 1;     // 64 rows
    const int warp_n = wid >> 1;    // 64 cols

    const int bid  = blockIdx.x;
    const int band = bid / (GROUP_M * TILES_N);
    const int rem  = bid % (GROUP_M * TILES_N);
    const int mt   = band * GROUP_M + (rem % GROUP_M);
    const int nt   = rem / GROUP_M;
    const int m0 = mt * 128;
    const int n0 = nt * 128;

    const uint32_t* Asrc = Apack + (size_t)(m0 >> 4) * 512 + tid * 4;
    const uint32_t* Bsrc = Bpack + (size_t)(n0 >> 4) * 512 + tid * 4;
    const size_t AstageStep = (size_t)MT16 * 512;
    const size_t BstageStep = (size_t)NT16 * 512;

    float acc[4][8][4];
#pragma unroll
    for (int mi = 0; mi < 4; mi++)
#pragma unroll
        for (int ni = 0; ni < 8; ni++)
#pragma unroll
            for (int q = 0; q < 4; q++) acc[mi][ni][q] = 0.0f;

    const int KT = KDIM / 32;    // 128
    const int aBase = warp_m * 4;
    const int bBase = warp_n * 4;

    // ---- prologue: stages 0 and 1 ----
#pragma unroll
    for (int s = 0; s < STAGES - 1; s++) {
        const uint32_t a_s = sbase + (uint32_t)(s * STAGE_WORDS) * 4;
        const uint32_t b_s = a_s + 4096 * 4;
#pragma unroll
        for (int i = 0; i < 8; i++) {
            cp16(a_s + tid * 16 + i * 2048, Asrc + (size_t)s * AstageStep + i * 512);
            cp16(b_s + tid * 16 + i * 2048, Bsrc + (size_t)s * BstageStep + i * 512);
        }
        asm volatile("cp.async.commit_group;" ::: "memory");
    }

    uint4 af[2][4], bf[2][4];

    // wait for stage0 and publish, then preload (0, ks0) fragments
    asm volatile("cp.async.wait_group %0;" :: "n"(STAGES - 2) : "memory");
    __syncthreads();
    {
        const uint32_t* as = smemu;
        const uint32_t* bs = as + 4096;
#pragma unroll
        for (int mi = 0; mi < 4; mi++)
            af[0][mi] = *reinterpret_cast<const uint4*>(
                as + (((aBase + mi) * 4 + 0) << 7) + lane * 4);
#pragma unroll
        for (int nj = 0; nj < 4; nj++)
            bf[0][nj] = *reinterpret_cast<const uint4*>(
                bs + (((bBase + nj) * 4 + 0) << 7) + lane * 4);
    }

    for (int kt = 0; kt < KT; kt++) {
        const uint32_t* as = smemu + (kt % STAGES) * STAGE_WORDS;
        const uint32_t* bs = as + 4096;

        // issue cp.async for stage kt+2 into slot (kt+2)%3 = (kt-1)%3.
        // Safe: all reads of that slot finished before the barrier at end of kt-1.
        const int kin = kt + STAGES - 1;
        if (kin < KT) {
            const int s = kin % STAGES;
            const uint32_t a_s = sbase + (uint32_t)(s * STAGE_WORDS) * 4;
            const uint32_t b_s = a_s + 4096 * 4;
#pragma unroll
            for (int i = 0; i < 8; i++) {
                cp16(a_s + tid * 16 + i * 2048, Asrc + (size_t)kin * AstageStep + i * 512);
                cp16(b_s + tid * 16 + i * 2048, Bsrc + (size_t)kin * BstageStep + i * 512);
            }
        }
        asm volatile("cp.async.commit_group;" ::: "memory");

        // ---- ks = 0..2: prefetch next frags, compute current ----
#pragma unroll
        for (int ks = 0; ks < 3; ks++) {
            const int cur = ks & 1;
            const int nxt = cur ^ 1;
#pragma unroll
            for (int mi = 0; mi < 4; mi++)
                af[nxt][mi] = *reinterpret_cast<const uint4*>(
                    as + (((aBase + mi) * 4 + ks + 1) << 7) + lane * 4);
#pragma unroll
            for (int nj = 0; nj < 4; nj++)
                bf[nxt][nj] = *reinterpret_cast<const uint4*>(
                    bs + (((bBase + nj) * 4 + ks + 1) << 7) + lane * 4);
#pragma unroll
            for (int mi = 0; mi < 4; mi++) {
                const uint32_t afr[4] = {af[cur][mi].x, af[cur][mi].y,
                                         af[cur][mi].z, af[cur][mi].w};
#pragma unroll
                for (int nj = 0; nj < 4; nj++) {
                    const uint32_t b0[2] = {bf[cur][nj].x, bf[cur][nj].z};
                    const uint32_t b1[2] = {bf[cur][nj].y, bf[cur][nj].w};
                    mma_tf32(acc[mi][nj * 2 + 0], afr, b0);
                    mma_tf32(acc[mi][nj * 2 + 1], afr, b1);
                }
            }
        }

        // ---- all stage-kt smem reads are done (ks3 frags live in buf1).
        // wait: my stage kt+1 cp groups complete ({kt+1, kt+2} outstanding -> kt+1 done).
        // barrier: publishes everyone's stage kt+1 AND licenses next kt's slot overwrite.
        asm volatile("cp.async.wait_group %0;" :: "n"(STAGES - 2) : "memory");
        __syncthreads();

        // ---- prefetch (kt+1, ks0) into buf0 (stage kt+1 now published) ----
        if (kt + 1 < KT) {
            const uint32_t* as2 = smemu + ((kt + 1) % STAGES) * STAGE_WORDS;
            const uint32_t* bs2 = as2 + 4096;
#pragma unroll
            for (int mi = 0; mi < 4; mi++)
                af[0][mi] = *reinterpret_cast<const uint4*>(
                    as2 + (((aBase + mi) * 4 + 0) << 7) + lane * 4);
#pragma unroll
            for (int nj = 0; nj < 4; nj++)
                bf[0][nj] = *reinterpret_cast<const uint4*>(
                    bs2 + (((bBase + nj) * 4 + 0) << 7) + lane * 4);
        }

        // ---- ks = 3 MMAs (buf1), covering the prefetch latency ----
#pragma unroll
        for (int mi = 0; mi < 4; mi++) {
            const uint32_t afr[4] = {af[1][mi].x, af[1][mi].y,
                                     af[1][mi].z, af[1][mi].w};
#pragma unroll
            for (int nj = 0; nj < 4; nj++) {
                const uint32_t b0[2] = {bf[1][nj].x, bf[1][nj].z};
                const uint32_t b1[2] = {bf[1][nj].y, bf[1][nj].w};
                mma_tf32(acc[mi][nj * 2 + 0], afr, b0);
                mma_tf32(acc[mi][nj * 2 + 1], afr, b1);
            }
        }
    }

    // ---- epilogue: bias + segmented store ----
    const int seg  = n0 / HDIM;
    const int nloc = n0 % HDIM;
    float* outseg = out + (size_t)seg * MDIM * HDIM;

#pragma unroll
    for (int ni = 0; ni < 8; ni++) {
        const int gn = n0 + warp_n * 64 + ni * 8 + 2 * tig;
        const float b0 = __ldg(bias + gn);
        const float b1 = __ldg(bias + gn + 1);
        const int cn = nloc + warp_n * 64 + ni * 8 + 2 * tig;
#pragma unroll
        for (int mi = 0; mi < 4; mi++) {
            const int gm = m0 + warp_m * 64 + mi * 16 + gid;
            float2 v0, v1;
            v0.x = acc[mi][ni][0] + b0;  v0.y = acc[mi][ni][1] + b1;
            v1.x = acc[mi][ni][2] + b0;  v1.y = acc[mi][ni][3] + b1;
            *reinterpret_cast<float2*>(outseg + (size_t)gm * HDIM + cn)       = v0;
            *reinterpret_cast<float2*>(outseg + (size_t)(gm + 8) * HDIM + cn) = v1;
        }
    }
}

extern "C" void kernel_launch(void* const* d_in, const int* in_sizes, int n_in,
                              void* d_out, int out_size)
{
    const float* x = (const float*)d_in[0];
    const float* W = (const float*)d_in[1];
    const float* b = (const float*)d_in[2];
    float* out = (float*)d_out;

    void *ap, *bp;
    cudaGetSymbolAddress(&ap, g_Apack);
    cudaGetSymbolAddress(&bp, g_Bpack);

    pack_a<<<32768, 256>>>(x, (uint32_t*)ap);
    pack_b<<<49152, 256>>>(W, (uint32_t*)bp);

    cudaFuncSetAttribute(gemm_tf32, cudaFuncAttributeMaxDynamicSharedMemorySize, SMEM_BYTES);
    gemm_tf32<<<TILES_M * TILES_N, THREADS, SMEM_BYTES>>>(
        (const uint32_t*)ap, (const uint32_t*)bp, b, out);
}

// round 10
// speedup vs baseline: 10.0136x; 2.0602x over previous
#include <cuda_runtime.h>
#include <cuda_fp16.h>
#include <cstdint>
#include <cstddef>

// ---------------------------------------------------------------------------
// Fused concat-linear, single-pass FP16 mma.sync.m16n8k16 (fp32 accumulate),
// fragment-packed operands. R9's pipeline structure (barrier off the critical
// path, fragment double-buffering) transplanted; BK=64 halves barrier count.
//   y[m,o] = sum_k x[m,k] W[o,k] + b[o];  M=8192 N=12288 K=4096
//   out = 3 segments of H=4096 along o.
// fp16 mantissa == tf32 mantissa (11 bits) -> same ~2.9e-4 rel err.
// ---------------------------------------------------------------------------

#define MDIM 8192
#define NDIM 12288
#define KDIM 4096
#define HDIM 4096

static constexpr int STAGES = 3;
static constexpr int THREADS = 128;

static constexpr int MT16 = MDIM / 16;        // 512
static constexpr int NT16 = NDIM / 16;        // 768
static constexpr int KC16 = KDIM / 16;        // 256

// packed half2-word scratch, fragment-ordered:
// A unit (kc16, mt16): 32 lanes x 4 words {a0,a1,a2,a3} of m16n8k16.row
// B unit (kc16, nt16): 32 lanes x 4 words {b0lo,b1lo,b0hi,b1hi} (two n8 frags)
__device__ uint32_t g_Apack[(size_t)KC16 * MT16 * 128];   // 67 MB
__device__ uint32_t g_Bpack[(size_t)KC16 * NT16 * 128];   // 100 MB

static constexpr int STAGE_WORDS = 8192;                       // A 16KB + B 16KB
static constexpr int SMEM_BYTES  = STAGES * STAGE_WORDS * 4;   // 98304

static constexpr int TILES_M = MDIM / 128;    // 64
static constexpr int TILES_N = NDIM / 128;    // 96
static constexpr int GROUP_M = 16;

__device__ __forceinline__ uint32_t smem_u32(const void* p) {
    return (uint32_t)__cvta_generic_to_shared(p);
}
__device__ __forceinline__ void cp16(uint32_t dst, const void* src) {
    asm volatile("cp.async.cg.shared.global [%0], [%1], 16;" :: "r"(dst), "l"(src));
}
__device__ __forceinline__ uint32_t h2pack(float lo, float hi) {
    __half2 h = __floats2half2_rn(lo, hi);
    return *reinterpret_cast<uint32_t*>(&h);
}
__device__ __forceinline__ void mma_f16(float* c, const uint32_t* a,
                                        uint32_t b0, uint32_t b1) {
    asm volatile(
        "mma.sync.aligned.m16n8k16.row.col.f32.f16.f16.f32 "
        "{%0,%1,%2,%3}, {%4,%5,%6,%7}, {%8,%9}, {%0,%1,%2,%3};"
        : "+f"(c[0]), "+f"(c[1]), "+f"(c[2]), "+f"(c[3])
        : "r"(a[0]), "r"(a[1]), "r"(a[2]), "r"(a[3]), "r"(b0), "r"(b1));
}

// ---------------- pack kernels ----------------
// A: unit = kc16 * MT16 + mt ; lane holds a0..a3 of the 16x16 subtile.
__global__ __launch_bounds__(256)
void pack_a(const float* __restrict__ src, uint32_t* __restrict__ dst) {
    const uint32_t idx = blockIdx.x * 256u + threadIdx.x;  // < 4194304
    const int lane = idx & 31;
    const uint32_t unit = idx >> 5;
    const int mt   = unit & 511;        // MT16 = 512
    const int kc16 = unit >> 9;
    const int gid = lane >> 2, tig = lane & 3;

    const float* r0 = src + (size_t)(mt * 16 + gid) * KDIM + kc16 * 16 + 2 * tig;
    const float* r1 = r0 + 8 * (size_t)KDIM;
    float2 v00 = *reinterpret_cast<const float2*>(r0);       // row,   k
    float2 v01 = *reinterpret_cast<const float2*>(r0 + 8);   // row,   k+8
    float2 v10 = *reinterpret_cast<const float2*>(r1);       // row+8, k
    float2 v11 = *reinterpret_cast<const float2*>(r1 + 8);   // row+8, k+8

    uint4 w;
    w.x = h2pack(v00.x, v00.y);   // a0
    w.y = h2pack(v10.x, v10.y);   // a1
    w.z = h2pack(v01.x, v01.y);   // a2
    w.w = h2pack(v11.x, v11.y);   // a3
    reinterpret_cast<uint4*>(dst)[idx] = w;
}
// B: unit = kc16 * NT16 + nt ; lane holds {b0,b1} for n-cols [nt*16+gid] and [+8].
__global__ __launch_bounds__(256)
void pack_b(const float* __restrict__ src, uint32_t* __restrict__ dst) {
    const uint32_t idx = blockIdx.x * 256u + threadIdx.x;  // < 6291456
    const int lane = idx & 31;
    const uint32_t unit = idx >> 5;
    const int nt   = unit % 768;        // NT16 = 768
    const int kc16 = unit / 768;
    const int gid = lane >> 2, tig = lane & 3;

    const float* r0 = src + (size_t)(nt * 16 + gid) * KDIM + kc16 * 16 + 2 * tig;
    const float* r1 = r0 + 8 * (size_t)KDIM;
    float2 v00 = *reinterpret_cast<const float2*>(r0);       // n,   k
    float2 v01 = *reinterpret_cast<const float2*>(r0 + 8);   // n,   k+8
    float2 v10 = *reinterpret_cast<const float2*>(r1);       // n+8, k
    float2 v11 = *reinterpret_cast<const float2*>(r1 + 8);   // n+8, k+8

    uint4 w;
    w.x = h2pack(v00.x, v00.y);   // b0 lower n8
    w.y = h2pack(v01.x, v01.y);   // b1 lower n8
    w.z = h2pack(v10.x, v10.y);   // b0 upper n8
    w.w = h2pack(v11.x, v11.y);   // b1 upper n8
    reinterpret_cast<uint4*>(dst)[idx] = w;
}

// ---------------- GEMM: 128x128 tile, BK=64, 4 warps of 64x64 ----------------
// stage layout (words): A [kc16(4)][mtile(8)][lane(32)][q(4)] = 4096,
//                       B [kc16(4)][ntile(8)][lane(32)][q(4)] = 4096 at +4096.
__global__ __launch_bounds__(THREADS, 2)
void gemm_f16(const uint32_t* __restrict__ Apack,
              const uint32_t* __restrict__ Bpack,
              const float* __restrict__ bias,
              float* __restrict__ out)
{
    extern __shared__ uint32_t smemu[];
    const uint32_t sbase = smem_u32(smemu);

    const int tid  = threadIdx.x;
    const int wid  = tid >> 5;
    const int lane = tid & 31;
    const int gid  = lane >> 2;
    const int tig  = lane & 3;
    const int warp_m = wid & 1;     // 64 rows
    const int warp_n = wid >> 1;    // 64 cols

    const int bid  = blockIdx.x;
    const int band = bid / (GROUP_M * TILES_N);
    const int rem  = bid % (GROUP_M * TILES_N);
    const int mt   = band * GROUP_M + (rem % GROUP_M);
    const int nt   = rem / GROUP_M;
    const int m0 = mt * 128;
    const int n0 = nt * 128;

    const int mtBase = m0 >> 4;     // 8 consecutive A units per kc16
    const int ntBase = n0 >> 4;     // 8 consecutive B units per kc16

    float acc[4][8][4];
#pragma unroll
    for (int mi = 0; mi < 4; mi++)
#pragma unroll
        for (int ni = 0; ni < 8; ni++)
#pragma unroll
            for (int q = 0; q < 4; q++) acc[mi][ni][q] = 0.0f;

    const int KT = KDIM / 64;       // 64
    const int aBase = warp_m * 4;
    const int bBase = warp_n * 4;

    // stage loader: 4 kc16 slabs x (A 4KB + B 4KB); 16 cp16 per thread
    auto load_stage = [&](int slot, int kt) {
        const uint32_t sA = sbase + (uint32_t)(slot * STAGE_WORDS) * 4;
        const uint32_t sB = sA + 4096 * 4;
#pragma unroll
        for (int kc = 0; kc < 4; kc++) {
            const uint32_t* aS = Apack + ((size_t)(4 * kt + kc) * MT16 + mtBase) * 128;
            const uint32_t* bS = Bpack + ((size_t)(4 * kt + kc) * NT16 + ntBase) * 128;
            cp16(sA + kc * 4096 + tid * 32,      aS + tid * 8);
            cp16(sA + kc * 4096 + tid * 32 + 16, aS + tid * 8 + 4);
            cp16(sB + kc * 4096 + tid * 32,      bS + tid * 8);
            cp16(sB + kc * 4096 + tid * 32 + 16, bS + tid * 8 + 4);
        }
        asm volatile("cp.async.commit_group;" ::: "memory");
    };

#pragma unroll
    for (int s = 0; s < STAGES - 1; s++) load_stage(s, s);

    uint4 af[2][4], bf[2][4];

    asm volatile("cp.async.wait_group %0;" :: "n"(STAGES - 2) : "memory");
    __syncthreads();
    {
        const uint32_t* as = smemu;
        const uint32_t* bs = as + 4096;
#pragma unroll
        for (int mi = 0; mi < 4; mi++)
            af[0][mi] = *reinterpret_cast<const uint4*>(
                as + (0 * 8 + aBase + mi) * 128 + lane * 4);
#pragma unroll
        for (int nj = 0; nj < 4; nj++)
            bf[0][nj] = *reinterpret_cast<const uint4*>(
                bs + (0 * 8 + bBase + nj) * 128 + lane * 4);
    }

    for (int kt = 0; kt < KT; kt++) {
        const uint32_t* as = smemu + (kt % STAGES) * STAGE_WORDS;
        const uint32_t* bs = as + 4096;

        const int kin = kt + STAGES - 1;
        if (kin < KT) load_stage(kin % STAGES, kin);
        else asm volatile("cp.async.commit_group;" ::: "memory");

        // ---- ks = 0..2: prefetch next frags, compute current ----
#pragma unroll
        for (int ks = 0; ks < 3; ks++) {
            const int cur = ks & 1;
            const int nxt = cur ^ 1;
#pragma unroll
            for (int mi = 0; mi < 4; mi++)
                af[nxt][mi] = *reinterpret_cast<const uint4*>(
                    as + ((ks + 1) * 8 + aBase + mi) * 128 + lane * 4);
#pragma unroll
            for (int nj = 0; nj < 4; nj++)
                bf[nxt][nj] = *reinterpret_cast<const uint4*>(
                    bs + ((ks + 1) * 8 + bBase + nj) * 128 + lane * 4);
#pragma unroll
            for (int mi = 0; mi < 4; mi++) {
                const uint32_t afr[4] = {af[cur][mi].x, af[cur][mi].y,
                                         af[cur][mi].z, af[cur][mi].w};
#pragma unroll
                for (int nj = 0; nj < 4; nj++) {
                    mma_f16(acc[mi][nj * 2 + 0], afr, bf[cur][nj].x, bf[cur][nj].y);
                    mma_f16(acc[mi][nj * 2 + 1], afr, bf[cur][nj].z, bf[cur][nj].w);
                }
            }
        }

        // ---- stage-kt smem reads done; publish stage kt+1, license slot reuse ----
        asm volatile("cp.async.wait_group %0;" :: "n"(STAGES - 2) : "memory");
        __syncthreads();

        // ---- prefetch (kt+1, ks0) into buf0 ----
        if (kt + 1 < KT) {
            const uint32_t* as2 = smemu + ((kt + 1) % STAGES) * STAGE_WORDS;
            const uint32_t* bs2 = as2 + 4096;
#pragma unroll
            for (int mi = 0; mi < 4; mi++)
                af[0][mi] = *reinterpret_cast<const uint4*>(
                    as2 + (aBase + mi) * 128 + lane * 4);
#pragma unroll
            for (int nj = 0; nj < 4; nj++)
                bf[0][nj] = *reinterpret_cast<const uint4*>(
                    bs2 + (bBase + nj) * 128 + lane * 4);
        }

        // ---- ks = 3 MMAs (buf1), covering the prefetch latency ----
#pragma unroll
        for (int mi = 0; mi < 4; mi++) {
            const uint32_t afr[4] = {af[1][mi].x, af[1][mi].y,
                                     af[1][mi].z, af[1][mi].w};
#pragma unroll
            for (int nj = 0; nj < 4; nj++) {
                mma_f16(acc[mi][nj * 2 + 0], afr, bf[1][nj].x, bf[1][nj].y);
                mma_f16(acc[mi][nj * 2 + 1], afr, bf[1][nj].z, bf[1][nj].w);
            }
        }
    }

    // ---- epilogue: bias + segmented store ----
    // acc[mi][ni]: cols = n0 + warp_n*64 + (ni>>1)*16 + (ni&1)*8 + 2*tig (+1)
    const int seg  = n0 / HDIM;
    const int nloc = n0 % HDIM;
    float* outseg = out + (size_t)seg * MDIM * HDIM;

#pragma unroll
    for (int ni = 0; ni < 8; ni++) {
        const int cofs = warp_n * 64 + (ni >> 1) * 16 + (ni & 1) * 8 + 2 * tig;
        const float b0 = __ldg(bias + n0 + cofs);
        const float b1 = __ldg(bias + n0 + cofs + 1);
        const int cn = nloc + cofs;
#pragma unroll
        for (int mi = 0; mi < 4; mi++) {
            const int gm = m0 + warp_m * 64 + mi * 16 + gid;
            float2 v0, v1;
            v0.x = acc[mi][ni][0] + b0;  v0.y = acc[mi][ni][1] + b1;
            v1.x = acc[mi][ni][2] + b0;  v1.y = acc[mi][ni][3] + b1;
            *reinterpret_cast<float2*>(outseg + (size_t)gm * HDIM + cn)       = v0;
            *reinterpret_cast<float2*>(outseg + (size_t)(gm + 8) * HDIM + cn) = v1;
        }
    }
}

extern "C" void kernel_launch(void* const* d_in, const int* in_sizes, int n_in,
                              void* d_out, int out_size)
{
    const float* x = (const float*)d_in[0];
    const float* W = (const float*)d_in[1];
    const float* b = (const float*)d_in[2];
    float* out = (float*)d_out;

    void *ap, *bp;
    cudaGetSymbolAddress(&ap, g_Apack);
    cudaGetSymbolAddress(&bp, g_Bpack);

    pack_a<<<16384, 256>>>(x, (uint32_t*)ap);
    pack_b<<<24576, 256>>>(W, (uint32_t*)bp);

    cudaFuncSetAttribute(gemm_f16, cudaFuncAttributeMaxDynamicSharedMemorySize, SMEM_BYTES);
    gemm_f16<<<TILES_M * TILES_N, THREADS, SMEM_BYTES>>>(
        (const uint32_t*)ap, (const uint32_t*)bp, b, out);
}

// round 11
// speedup vs baseline: 10.0348x; 1.0021x over previous
#include <cuda_runtime.h>
#include <cuda_fp16.h>
#include <cstdint>
#include <cstddef>

// ---------------------------------------------------------------------------
// Fused concat-linear, single-pass FP16 mma.sync.m16n8k16 (fp32 accumulate),
// fragment-packed operands. R10 GEMM core (92% tensor) untouched.
// R11: packs fused into one kernel (launch overlap), GROUP_M=32 halves the
// B DRAM refetch during the mainloop.
// ---------------------------------------------------------------------------

#define MDIM 8192
#define NDIM 12288
#define KDIM 4096
#define HDIM 4096

static constexpr int STAGES = 3;
static constexpr int THREADS = 128;

static constexpr int MT16 = MDIM / 16;        // 512
static constexpr int NT16 = NDIM / 16;        // 768
static constexpr int KC16 = KDIM / 16;        // 256

// packed half2-word scratch, fragment-ordered (validated R10):
// A unit (kc16, mt16): 32 lanes x 4 words {a0,a1,a2,a3} of m16n8k16.row
// B unit (kc16, nt16): 32 lanes x 4 words {b0lo,b1lo,b0hi,b1hi}
__device__ uint32_t g_Apack[(size_t)KC16 * MT16 * 128];   // 67 MB
__device__ uint32_t g_Bpack[(size_t)KC16 * NT16 * 128];   // 100 MB

static constexpr int STAGE_WORDS = 8192;                       // A 16KB + B 16KB
static constexpr int SMEM_BYTES  = STAGES * STAGE_WORDS * 4;   // 98304

static constexpr int TILES_M = MDIM / 128;    // 64
static constexpr int TILES_N = NDIM / 128;    // 96
static constexpr int GROUP_M = 32;            // R11: 16 -> 32 (B refetch halved)

static constexpr int A_PACK_BLOCKS = 16384;   // 4194304 threads
static constexpr int B_PACK_BLOCKS = 24576;   // 6291456 threads

__device__ __forceinline__ uint32_t smem_u32(const void* p) {
    return (uint32_t)__cvta_generic_to_shared(p);
}
__device__ __forceinline__ void cp16(uint32_t dst, const void* src) {
    asm volatile("cp.async.cg.shared.global [%0], [%1], 16;" :: "r"(dst), "l"(src));
}
__device__ __forceinline__ uint32_t h2pack(float lo, float hi) {
    __half2 h = __floats2half2_rn(lo, hi);
    return *reinterpret_cast<uint32_t*>(&h);
}
__device__ __forceinline__ void mma_f16(float* c, const uint32_t* a,
                                        uint32_t b0, uint32_t b1) {
    asm volatile(
        "mma.sync.aligned.m16n8k16.row.col.f32.f16.f16.f32 "
        "{%0,%1,%2,%3}, {%4,%5,%6,%7}, {%8,%9}, {%0,%1,%2,%3};"
        : "+f"(c[0]), "+f"(c[1]), "+f"(c[2]), "+f"(c[3])
        : "r"(a[0]), "r"(a[1]), "r"(a[2]), "r"(a[3]), "r"(b0), "r"(b1));
}

// ---------------- fused pack kernel ----------------
// blocks [0, A_PACK_BLOCKS)            -> A units
// blocks [A_PACK_BLOCKS, +B_PACK_BLOCKS) -> B units
__global__ __launch_bounds__(256)
void pack_ab(const float* __restrict__ xsrc, const float* __restrict__ wsrc,
             uint32_t* __restrict__ dstA, uint32_t* __restrict__ dstB) {
    if (blockIdx.x < A_PACK_BLOCKS) {
        const uint32_t idx = blockIdx.x * 256u + threadIdx.x;    // < 4194304
        const int lane = idx & 31;
        const uint32_t unit = idx >> 5;
        const int mt   = unit & 511;        // MT16 = 512
        const int kc16 = unit >> 9;
        const int gid = lane >> 2, tig = lane & 3;

        const float* r0 = xsrc + (size_t)(mt * 16 + gid) * KDIM + kc16 * 16 + 2 * tig;
        const float* r1 = r0 + 8 * (size_t)KDIM;
        float2 v00 = *reinterpret_cast<const float2*>(r0);       // row,   k
        float2 v01 = *reinterpret_cast<const float2*>(r0 + 8);   // row,   k+8
        float2 v10 = *reinterpret_cast<const float2*>(r1);       // row+8, k
        float2 v11 = *reinterpret_cast<const float2*>(r1 + 8);   // row+8, k+8

        uint4 w;
        w.x = h2pack(v00.x, v00.y);   // a0
        w.y = h2pack(v10.x, v10.y);   // a1
        w.z = h2pack(v01.x, v01.y);   // a2
        w.w = h2pack(v11.x, v11.y);   // a3
        reinterpret_cast<uint4*>(dstA)[idx] = w;
    } else {
        const uint32_t idx = (blockIdx.x - A_PACK_BLOCKS) * 256u + threadIdx.x; // < 6291456
        const int lane = idx & 31;
        const uint32_t unit = idx >> 5;
        const int nt   = unit % 768;        // NT16 = 768
        const int kc16 = unit / 768;
        const int gid = lane >> 2, tig = lane & 3;

        const float* r0 = wsrc + (size_t)(nt * 16 + gid) * KDIM + kc16 * 16 + 2 * tig;
        const float* r1 = r0 + 8 * (size_t)KDIM;
        float2 v00 = *reinterpret_cast<const float2*>(r0);       // n,   k
        float2 v01 = *reinterpret_cast<const float2*>(r0 + 8);   // n,   k+8
        float2 v10 = *reinterpret_cast<const float2*>(r1);       // n+8, k
        float2 v11 = *reinterpret_cast<const float2*>(r1 + 8);   // n+8, k+8

        uint4 w;
        w.x = h2pack(v00.x, v00.y);   // b0 lower n8
        w.y = h2pack(v01.x, v01.y);   // b1 lower n8
        w.z = h2pack(v10.x, v10.y);   // b0 upper n8
        w.w = h2pack(v11.x, v11.y);   // b1 upper n8
        reinterpret_cast<uint4*>(dstB)[idx] = w;
    }
}

// ---------------- GEMM: 128x128 tile, BK=64, 4 warps of 64x64 (R10 core) ----------------
// stage layout (words): A [kc16(4)][mtile(8)][lane(32)][q(4)] = 4096,
//                       B [kc16(4)][ntile(8)][lane(32)][q(4)] = 4096 at +4096.
__global__ __launch_bounds__(THREADS, 2)
void gemm_f16(const uint32_t* __restrict__ Apack,
              const uint32_t* __restrict__ Bpack,
              const float* __restrict__ bias,
              float* __restrict__ out)
{
    extern __shared__ uint32_t smemu[];
    const uint32_t sbase = smem_u32(smemu);

    const int tid  = threadIdx.x;
    const int wid  = tid >> 5;
    const int lane = tid & 31;
    const int gid  = lane >> 2;
    const int tig  = lane & 3;
    const int warp_m = wid & 1;     // 64 rows
    const int warp_n = wid >> 1;    // 64 cols

    const int bid  = blockIdx.x;
    const int band = bid / (GROUP_M * TILES_N);
    const int rem  = bid % (GROUP_M * TILES_N);
    const int mt   = band * GROUP_M + (rem % GROUP_M);
    const int nt   = rem / GROUP_M;
    const int m0 = mt * 128;
    const int n0 = nt * 128;

    const int mtBase = m0 >> 4;     // 8 consecutive A units per kc16
    const int ntBase = n0 >> 4;     // 8 consecutive B units per kc16

    float acc[4][8][4];
#pragma unroll
    for (int mi = 0; mi < 4; mi++)
#pragma unroll
        for (int ni = 0; ni < 8; ni++)
#pragma unroll
            for (int q = 0; q < 4; q++) acc[mi][ni][q] = 0.0f;

    const int KT = KDIM / 64;       // 64
    const int aBase = warp_m * 4;
    const int bBase = warp_n * 4;

    auto load_stage = [&](int slot, int kt) {
        const uint32_t sA = sbase + (uint32_t)(slot * STAGE_WORDS) * 4;
        const uint32_t sB = sA + 4096 * 4;
#pragma unroll
        for (int kc = 0; kc < 4; kc++) {
            const uint32_t* aS = Apack + ((size_t)(4 * kt + kc) * MT16 + mtBase) * 128;
            const uint32_t* bS = Bpack + ((size_t)(4 * kt + kc) * NT16 + ntBase) * 128;
            cp16(sA + kc * 4096 + tid * 32,      aS + tid * 8);
            cp16(sA + kc * 4096 + tid * 32 + 16, aS + tid * 8 + 4);
            cp16(sB + kc * 4096 + tid * 32,      bS + tid * 8);
            cp16(sB + kc * 4096 + tid * 32 + 16, bS + tid * 8 + 4);
        }
        asm volatile("cp.async.commit_group;" ::: "memory");
    };

#pragma unroll
    for (int s = 0; s < STAGES - 1; s++) load_stage(s, s);

    uint4 af[2][4], bf[2][4];

    asm volatile("cp.async.wait_group %0;" :: "n"(STAGES - 2) : "memory");
    __syncthreads();
    {
        const uint32_t* as = smemu;
        const uint32_t* bs = as + 4096;
#pragma unroll
        for (int mi = 0; mi < 4; mi++)
            af[0][mi] = *reinterpret_cast<const uint4*>(
                as + (aBase + mi) * 128 + lane * 4);
#pragma unroll
        for (int nj = 0; nj < 4; nj++)
            bf[0][nj] = *reinterpret_cast<const uint4*>(
                bs + (bBase + nj) * 128 + lane * 4);
    }

    for (int kt = 0; kt < KT; kt++) {
        const uint32_t* as = smemu + (kt % STAGES) * STAGE_WORDS;
        const uint32_t* bs = as + 4096;

        const int kin = kt + STAGES - 1;
        if (kin < KT) load_stage(kin % STAGES, kin);
        else asm volatile("cp.async.commit_group;" ::: "memory");

        // ---- ks = 0..2: prefetch next frags, compute current ----
#pragma unroll
        for (int ks = 0; ks < 3; ks++) {
            const int cur = ks & 1;
            const int nxt = cur ^ 1;
#pragma unroll
            for (int mi = 0; mi < 4; mi++)
                af[nxt][mi] = *reinterpret_cast<const uint4*>(
                    as + ((ks + 1) * 8 + aBase + mi) * 128 + lane * 4);
#pragma unroll
            for (int nj = 0; nj < 4; nj++)
                bf[nxt][nj] = *reinterpret_cast<const uint4*>(
                    bs + ((ks + 1) * 8 + bBase + nj) * 128 + lane * 4);
#pragma unroll
            for (int mi = 0; mi < 4; mi++) {
                const uint32_t afr[4] = {af[cur][mi].x, af[cur][mi].y,
                                         af[cur][mi].z, af[cur][mi].w};
#pragma unroll
                for (int nj = 0; nj < 4; nj++) {
                    mma_f16(acc[mi][nj * 2 + 0], afr, bf[cur][nj].x, bf[cur][nj].y);
                    mma_f16(acc[mi][nj * 2 + 1], afr, bf[cur][nj].z, bf[cur][nj].w);
                }
            }
        }

        // ---- stage-kt smem reads done; publish stage kt+1, license slot reuse ----
        asm volatile("cp.async.wait_group %0;" :: "n"(STAGES - 2) : "memory");
        __syncthreads();

        // ---- prefetch (kt+1, ks0) into buf0 ----
        if (kt + 1 < KT) {
            const uint32_t* as2 = smemu + ((kt + 1) % STAGES) * STAGE_WORDS;
            const uint32_t* bs2 = as2 + 4096;
#pragma unroll
            for (int mi = 0; mi < 4; mi++)
                af[0][mi] = *reinterpret_cast<const uint4*>(
                    as2 + (aBase + mi) * 128 + lane * 4);
#pragma unroll
            for (int nj = 0; nj < 4; nj++)
                bf[0][nj] = *reinterpret_cast<const uint4*>(
                    bs2 + (bBase + nj) * 128 + lane * 4);
        }

        // ---- ks = 3 MMAs (buf1), covering the prefetch latency ----
#pragma unroll
        for (int mi = 0; mi < 4; mi++) {
            const uint32_t afr[4] = {af[1][mi].x, af[1][mi].y,
                                     af[1][mi].z, af[1][mi].w};
#pragma unroll
            for (int nj = 0; nj < 4; nj++) {
                mma_f16(acc[mi][nj * 2 + 0], afr, bf[1][nj].x, bf[1][nj].y);
                mma_f16(acc[mi][nj * 2 + 1], afr, bf[1][nj].z, bf[1][nj].w);
            }
        }
    }

    // ---- epilogue: bias + segmented store ----
    const int seg  = n0 / HDIM;
    const int nloc = n0 % HDIM;
    float* outseg = out + (size_t)seg * MDIM * HDIM;

#pragma unroll
    for (int ni = 0; ni < 8; ni++) {
        const int cofs = warp_n * 64 + (ni >> 1) * 16 + (ni & 1) * 8 + 2 * tig;
        const float b0 = __ldg(bias + n0 + cofs);
        const float b1 = __ldg(bias + n0 + cofs + 1);
        const int cn = nloc + cofs;
#pragma unroll
        for (int mi = 0; mi < 4; mi++) {
            const int gm = m0 + warp_m * 64 + mi * 16 + gid;
            float2 v0, v1;
            v0.x = acc[mi][ni][0] + b0;  v0.y = acc[mi][ni][1] + b1;
            v1.x = acc[mi][ni][2] + b0;  v1.y = acc[mi][ni][3] + b1;
            *reinterpret_cast<float2*>(outseg + (size_t)gm * HDIM + cn)       = v0;
            *reinterpret_cast<float2*>(outseg + (size_t)(gm + 8) * HDIM + cn) = v1;
        }
    }
}

extern "C" void kernel_launch(void* const* d_in, const int* in_sizes, int n_in,
                              void* d_out, int out_size)
{
    const float* x = (const float*)d_in[0];
    const float* W = (const float*)d_in[1];
    const float* b = (const float*)d_in[2];
    float* out = (float*)d_out;

    void *ap, *bp;
    cudaGetSymbolAddress(&ap, g_Apack);
    cudaGetSymbolAddress(&bp, g_Bpack);

    pack_ab<<<A_PACK_BLOCKS + B_PACK_BLOCKS, 256>>>(
        x, W, (uint32_t*)ap, (uint32_t*)bp);

    cudaFuncSetAttribute(gemm_f16, cudaFuncAttributeMaxDynamicSharedMemorySize, SMEM_BYTES);
    gemm_f16<<<TILES_M * TILES_N, THREADS, SMEM_BYTES>>>(
        (const uint32_t*)ap, (const uint32_t*)bp, b, out);
}